// round 2
// baseline (speedup 1.0000x reference)
#include <cuda_runtime.h>
#include <math.h>

#define BATCH 4
#define LSEQ  2048
#define HDIM  2048
#define NHEADS 16
#define HD    128

// ---------------- scratch (no allocations allowed) ----------------
__device__ float g_qkv[(size_t)BATCH * LSEQ * 3 * HDIM];   // (B*L, 3H)
__device__ float g_q[(size_t)BATCH * NHEADS * LSEQ * HD];  // (B,NH,L,HD)
__device__ float g_k[(size_t)BATCH * NHEADS * LSEQ * HD];
__device__ float g_v[(size_t)BATCH * NHEADS * LSEQ * HD];
__device__ float g_y[(size_t)BATCH * LSEQ * HDIM];         // (B*L, H)

// ---------------- packed f32x2 helpers (Blackwell FFMA2 path) ----------------
#define FMA2(d, a, b) asm("fma.rn.f32x2 %0, %1, %2, %0;" : "+l"(d) : "l"(a), "l"(b))
#define PACK2(d, lo, hi) asm("mov.b64 %0, {%1, %2};" : "=l"(d) : "f"(lo), "f"(hi))
#define UNPK2(lo, hi, d) asm("mov.b64 {%0, %1}, %2;" : "=f"(lo), "=f"(hi) : "l"(d))

// ============================================================================
// SGEMM: C[M,N] = A[M,K] @ B[K,N] + bias[N]  (optional SiLU epilogue)
// 128x128 tile, K-tile 8, 256 threads, 8x8 microtile, f32x2 accumulators.
// M,N,K all multiples of 128/8 for this problem — no bounds checks.
// ============================================================================
template <bool SILU>
__global__ __launch_bounds__(256) void sgemm_bias(
    const float* __restrict__ A, const float* __restrict__ B,
    const float* __restrict__ bias, float* __restrict__ C,
    int M, int N, int K)
{
    __shared__ float As[8][128];   // As[k][m]
    __shared__ float Bs[8][128];   // Bs[k][n]

    const int t  = threadIdx.x;
    const int tx = t & 15, ty = t >> 4;
    const int tm = blockIdx.y * 128, tn = blockIdx.x * 128;

    const int a_row = t >> 1,  a_k   = (t & 1) << 2;   // 128 rows x 8 k
    const int b_row = t >> 5,  b_col = (t & 31) << 2;  // 8 rows x 128 n

    const float* Ap = A + (size_t)(tm + a_row) * K + a_k;
    const float* Bp = B + (size_t)b_row * N + tn + b_col;

    unsigned long long acc[8][4];
#pragma unroll
    for (int i = 0; i < 8; i++)
#pragma unroll
        for (int j = 0; j < 4; j++) acc[i][j] = 0ULL;

    for (int k0 = 0; k0 < K; k0 += 8) {
        float4 av = *(const float4*)Ap;
        float4 bv = *(const float4*)Bp;
        __syncthreads();
        As[a_k + 0][a_row] = av.x;
        As[a_k + 1][a_row] = av.y;
        As[a_k + 2][a_row] = av.z;
        As[a_k + 3][a_row] = av.w;
        *(float4*)&Bs[b_row][b_col] = bv;
        __syncthreads();
        Ap += 8;
        Bp += (size_t)8 * N;

#pragma unroll
        for (int kk = 0; kk < 8; kk++) {
            float4 a0 = *(const float4*)&As[kk][ty * 8];
            float4 a1 = *(const float4*)&As[kk][ty * 8 + 4];
            const unsigned long long* bq =
                (const unsigned long long*)&Bs[kk][tx * 8];
            unsigned long long b2[4];
            b2[0] = bq[0]; b2[1] = bq[1]; b2[2] = bq[2]; b2[3] = bq[3];
            float ra[8] = {a0.x, a0.y, a0.z, a0.w, a1.x, a1.y, a1.z, a1.w};
#pragma unroll
            for (int i = 0; i < 8; i++) {
                unsigned long long a2;
                PACK2(a2, ra[i], ra[i]);
#pragma unroll
                for (int j = 0; j < 4; j++) FMA2(acc[i][j], a2, b2[j]);
            }
        }
    }

    // epilogue
    float bvls[8];
#pragma unroll
    for (int j = 0; j < 8; j++) bvls[j] = bias[tn + tx * 8 + j];

#pragma unroll
    for (int i = 0; i < 8; i++) {
        float vals[8];
#pragma unroll
        for (int j = 0; j < 4; j++) UNPK2(vals[2 * j], vals[2 * j + 1], acc[i][j]);
        float o[8];
#pragma unroll
        for (int j = 0; j < 8; j++) {
            float v = vals[j] + bvls[j];
            if (SILU) v = v / (1.0f + __expf(-v));
            o[j] = v;
        }
        float* Cp = C + (size_t)(tm + ty * 8 + i) * N + tn + tx * 8;
        *(float4*)Cp       = make_float4(o[0], o[1], o[2], o[3]);
        *(float4*)(Cp + 4) = make_float4(o[4], o[5], o[6], o[7]);
    }
}

// ============================================================================
// RoPE + head scatter.
// qkv row (b,l): q = cols[0:2048), k = cols[2048:4096), v = cols[4096:6144).
// RoPE pairs (i, i+1024) over the full 2048 dims with cos/sin[l][i].
// Heads: full-dim index j -> head h = j%16, dim d = j/16   (reshape(.., HD, NH)).
// Output layout (b, h, l, d) contiguous in d.
// One block per (b,l) row; stage per-head-major in shared, write coalesced.
// ============================================================================
__global__ __launch_bounds__(256) void rope_scatter(
    const float* __restrict__ qkv,
    const float* __restrict__ cosT, const float* __restrict__ sinT,
    float* __restrict__ Q, float* __restrict__ Kv, float* __restrict__ V)
{
    const int bl = blockIdx.x;
    const int b = bl >> 11, l = bl & 2047;
    const float* row = qkv + (size_t)bl * (3 * HDIM);
    const float* cr = cosT + (size_t)l * (HDIM / 2);
    const float* sr = sinT + (size_t)l * (HDIM / 2);

    __shared__ float buf[NHEADS * 132];  // buf[h*132 + d]
    const int warp = threadIdx.x >> 5, lane = threadIdx.x & 31;

    // ---- Q (rotary) ----
    for (int i = threadIdx.x; i < HDIM / 2; i += 256) {
        float u1 = row[i], u2 = row[i + HDIM / 2];
        float c = cr[i], s = sr[i];
        int h = i & 15, d = i >> 4;          // d in [0,64)
        buf[h * 132 + d]      = u1 * c + u2 * s;
        buf[h * 132 + d + 64] = -u1 * s + u2 * c;
    }
    __syncthreads();
    for (int h = warp * 2; h < warp * 2 + 2; h++) {
        float* dst = Q + ((size_t)(b * NHEADS + h) * LSEQ + l) * HD;
        for (int d = lane; d < HD; d += 32) dst[d] = buf[h * 132 + d];
    }
    __syncthreads();

    // ---- K (rotary) ----
    for (int i = threadIdx.x; i < HDIM / 2; i += 256) {
        float u1 = row[HDIM + i], u2 = row[HDIM + i + HDIM / 2];
        float c = cr[i], s = sr[i];
        int h = i & 15, d = i >> 4;
        buf[h * 132 + d]      = u1 * c + u2 * s;
        buf[h * 132 + d + 64] = -u1 * s + u2 * c;
    }
    __syncthreads();
    for (int h = warp * 2; h < warp * 2 + 2; h++) {
        float* dst = Kv + ((size_t)(b * NHEADS + h) * LSEQ + l) * HD;
        for (int d = lane; d < HD; d += 32) dst[d] = buf[h * 132 + d];
    }
    __syncthreads();

    // ---- V (no rotary) ----
    for (int i = threadIdx.x; i < HDIM; i += 256) {
        int h = i & 15, d = i >> 4;
        buf[h * 132 + d] = row[2 * HDIM + i];
    }
    __syncthreads();
    for (int h = warp * 2; h < warp * 2 + 2; h++) {
        float* dst = V + ((size_t)(b * NHEADS + h) * LSEQ + l) * HD;
        for (int d = lane; d < HD; d += 32) dst[d] = buf[h * 132 + d];
    }
}

// ============================================================================
// Flash attention (causal), fp32. BM=BN=64, HD=128, 256 threads (16x16).
// Thread (ty,tx) owns S rows {ty+16i}, cols {tx+16j} (strided to dodge bank
// conflicts), O cols {tx+16j, j<8}. Online softmax; shuffle row-reductions
// (xor offsets 8/4/2/1 stay inside the 16-lane tx group).
// Writes attention output already inverse-head-mapped: y[b,l, h*128+d].
// ============================================================================
#define BM 64
#define BN 64
__global__ __launch_bounds__(256) void flash_attn(
    const float* __restrict__ Q, const float* __restrict__ K,
    const float* __restrict__ V, float* __restrict__ Y)
{
    extern __shared__ float sm[];
    float (*Qs)[132] = (float(*)[132])sm;                    // [64][132]
    float (*Ks)[132] = (float(*)[132])(sm + 64 * 132);
    float (*Vs)[132] = (float(*)[132])(sm + 2 * 64 * 132);
    float (*Ps)[65]  = (float(*)[65])(sm + 3 * 64 * 132);    // [64][65]

    const int qb = blockIdx.x, bh = blockIdx.y;
    const int b = bh >> 4, h = bh & 15;
    const size_t base = (size_t)bh * LSEQ * HD;
    const int t = threadIdx.x, tx = t & 15, ty = t >> 4;
    const float scale = 0.08838834764831845f;  // 1/sqrt(128)

    // load Q tile
    {
        const float* Qg = Q + base + (size_t)qb * BM * HD;
        for (int f = t; f < BM * HD / 4; f += 256) {
            int pos = f * 4, r = pos >> 7, d = pos & 127;
            *(float4*)&Qs[r][d] = *(const float4*)&Qg[pos];
        }
    }

    float acc[4][8];
#pragma unroll
    for (int i = 0; i < 4; i++)
#pragma unroll
        for (int j = 0; j < 8; j++) acc[i][j] = 0.0f;
    float mi[4], li[4];
#pragma unroll
    for (int i = 0; i < 4; i++) { mi[i] = -1e30f; li[i] = 0.0f; }

    for (int kb = 0; kb <= qb; kb++) {
        __syncthreads();   // previous iteration fully read Ks/Vs/Ps
        {
            const float* Kg = K + base + (size_t)kb * BN * HD;
            const float* Vg = V + base + (size_t)kb * BN * HD;
            for (int f = t; f < BN * HD / 4; f += 256) {
                int pos = f * 4, r = pos >> 7, d = pos & 127;
                *(float4*)&Ks[r][d] = *(const float4*)&Kg[pos];
                *(float4*)&Vs[r][d] = *(const float4*)&Vg[pos];
            }
        }
        __syncthreads();

        float s[4][4];
#pragma unroll
        for (int i = 0; i < 4; i++)
#pragma unroll
            for (int j = 0; j < 4; j++) s[i][j] = 0.0f;

#pragma unroll 4
        for (int kk = 0; kk < HD; kk++) {
            float ra[4], rb[4];
#pragma unroll
            for (int i = 0; i < 4; i++) ra[i] = Qs[ty + i * 16][kk];
#pragma unroll
            for (int j = 0; j < 4; j++) rb[j] = Ks[tx + j * 16][kk];
#pragma unroll
            for (int i = 0; i < 4; i++)
#pragma unroll
                for (int j = 0; j < 4; j++) s[i][j] += ra[i] * rb[j];
        }

#pragma unroll
        for (int i = 0; i < 4; i++)
#pragma unroll
            for (int j = 0; j < 4; j++) s[i][j] *= scale;

        if (kb == qb) {  // causal mask on diagonal block
#pragma unroll
            for (int i = 0; i < 4; i++)
#pragma unroll
                for (int j = 0; j < 4; j++)
                    if (tx + j * 16 > ty + i * 16) s[i][j] = -1e30f;
        }

        // online softmax update
#pragma unroll
        for (int i = 0; i < 4; i++) {
            float v = fmaxf(fmaxf(s[i][0], s[i][1]), fmaxf(s[i][2], s[i][3]));
#pragma unroll
            for (int off = 8; off >= 1; off >>= 1)
                v = fmaxf(v, __shfl_xor_sync(0xffffffffu, v, off));
            float mnew = fmaxf(mi[i], v);
            float alpha = __expf(mi[i] - mnew);
            float sum = 0.0f;
#pragma unroll
            for (int j = 0; j < 4; j++) {
                float p = __expf(s[i][j] - mnew);
                Ps[ty + i * 16][tx + j * 16] = p;
                sum += p;
            }
#pragma unroll
            for (int off = 8; off >= 1; off >>= 1)
                sum += __shfl_xor_sync(0xffffffffu, sum, off);
            li[i] = li[i] * alpha + sum;
            mi[i] = mnew;
#pragma unroll
            for (int j = 0; j < 8; j++) acc[i][j] *= alpha;
        }
        __syncthreads();

        // O += P @ V
#pragma unroll 4
        for (int kk = 0; kk < BN; kk++) {
            float pv[4], vv[8];
#pragma unroll
            for (int i = 0; i < 4; i++) pv[i] = Ps[ty + i * 16][kk];
#pragma unroll
            for (int j = 0; j < 8; j++) vv[j] = Vs[kk][tx + j * 16];
#pragma unroll
            for (int i = 0; i < 4; i++)
#pragma unroll
                for (int j = 0; j < 8; j++) acc[i][j] += pv[i] * vv[j];
        }
    }

    // epilogue: y[b, l, h*128 + d]  (inverse of to_heads: (b,l,NH,HD) concat)
#pragma unroll
    for (int i = 0; i < 4; i++) {
        int l = qb * BM + ty + i * 16;
        float inv = 1.0f / li[i];
        float* dst = Y + (size_t)(b * LSEQ + l) * HDIM + h * HD;
#pragma unroll
        for (int j = 0; j < 8; j++) dst[tx + j * 16] = acc[i][j] * inv;
    }
}

// ============================================================================
// launch
// ============================================================================
extern "C" void kernel_launch(void* const* d_in, const int* in_sizes, int n_in,
                              void* d_out, int out_size)
{
    const float* x    = (const float*)d_in[0];
    const float* Wqkv = (const float*)d_in[1];
    const float* bqkv = (const float*)d_in[2];
    const float* Wfc2 = (const float*)d_in[3];
    const float* bfc2 = (const float*)d_in[4];
    const float* cosT = (const float*)d_in[5];
    const float* sinT = (const float*)d_in[6];
    float* out = (float*)d_out;

    float *qkv, *q, *k, *v, *y;
    cudaGetSymbolAddress((void**)&qkv, g_qkv);
    cudaGetSymbolAddress((void**)&q, g_q);
    cudaGetSymbolAddress((void**)&k, g_k);
    cudaGetSymbolAddress((void**)&v, g_v);
    cudaGetSymbolAddress((void**)&y, g_y);

    const int M = BATCH * LSEQ;  // 8192

    // 1) qkv = x @ Wqkv + bqkv
    dim3 g1((3 * HDIM) / 128, M / 128);
    sgemm_bias<false><<<g1, 256>>>(x, Wqkv, bqkv, qkv, M, 3 * HDIM, HDIM);

    // 2) RoPE + head scatter
    rope_scatter<<<M, 256>>>(qkv, cosT, sinT, q, k, v);

    // 3) causal flash attention
    int smem = (3 * 64 * 132 + 64 * 65) * (int)sizeof(float);
    cudaFuncSetAttribute(flash_attn, cudaFuncAttributeMaxDynamicSharedMemorySize, smem);
    flash_attn<<<dim3(LSEQ / BM, BATCH * NHEADS), 256, smem>>>(q, k, v, y);

    // 4) out = silu(y @ Wfc2 + bfc2)
    dim3 g2(HDIM / 128, M / 128);
    sgemm_bias<true><<<g2, 256>>>(y, Wfc2, bfc2, out, M, HDIM, HDIM);
}

// round 10
// speedup vs baseline: 1.5601x; 1.5601x over previous
#include <cuda_runtime.h>
#include <cuda_bf16.h>
#include <stdint.h>
#include <math.h>

#define BATCH 4
#define LSEQ  2048
#define HDIM  2048
#define NHEADS 16
#define HD    128

// ---------------- scratch (no allocations allowed) ----------------
__device__ __align__(16) float g_qkv[(size_t)BATCH * LSEQ * 3 * HDIM];   // (B*L, 3H)
__device__ __align__(16) float g_q[(size_t)BATCH * NHEADS * LSEQ * HD];  // (B,NH,L,HD)
__device__ __align__(16) float g_k[(size_t)BATCH * NHEADS * LSEQ * HD];
__device__ __align__(16) float g_v[(size_t)BATCH * NHEADS * LSEQ * HD];
__device__ __align__(16) float g_y[(size_t)BATCH * LSEQ * HDIM];         // (B*L, H)

// bf16 split operands
__device__ __align__(16) __nv_bfloat16 g_xhi[(size_t)BATCH * LSEQ * HDIM];
__device__ __align__(16) __nv_bfloat16 g_xlo[(size_t)BATCH * LSEQ * HDIM];
__device__ __align__(16) __nv_bfloat16 g_yhi[(size_t)BATCH * LSEQ * HDIM];
__device__ __align__(16) __nv_bfloat16 g_ylo[(size_t)BATCH * LSEQ * HDIM];
__device__ __align__(16) __nv_bfloat16 g_w1hi[(size_t)3 * HDIM * HDIM];  // [6144, 2048] (N,K)
__device__ __align__(16) __nv_bfloat16 g_w1lo[(size_t)3 * HDIM * HDIM];
__device__ __align__(16) __nv_bfloat16 g_w2hi[(size_t)HDIM * HDIM];      // [2048, 2048]
__device__ __align__(16) __nv_bfloat16 g_w2lo[(size_t)HDIM * HDIM];

// ---------------- helpers ----------------
__device__ __forceinline__ uint32_t smem_u32(const void* p) {
    uint32_t a;
    asm("{ .reg .u64 t; cvta.to.shared.u64 t, %1; cvt.u32.u64 %0, t; }" : "=r"(a) : "l"(p));
    return a;
}
#define CP_ASYNC16(dst, src) \
    asm volatile("cp.async.cg.shared.global [%0], [%1], 16;" :: "r"(dst), "l"(src))
#define CP_COMMIT() asm volatile("cp.async.commit_group;" ::: "memory")
#define CP_WAIT(n)  asm volatile("cp.async.wait_group %0;" :: "n"(n) : "memory")

#define LDSM4(r0, r1, r2, r3, addr) \
    asm volatile("ldmatrix.sync.aligned.m8n8.x4.shared.b16 {%0,%1,%2,%3}, [%4];" \
                 : "=r"(r0), "=r"(r1), "=r"(r2), "=r"(r3) : "r"(addr))

#define MMA16816(d, a, b) \
    asm volatile("mma.sync.aligned.m16n8k16.row.col.f32.bf16.bf16.f32 " \
                 "{%0,%1,%2,%3}, {%4,%5,%6,%7}, {%8,%9}, {%0,%1,%2,%3};" \
                 : "+f"((d)[0]), "+f"((d)[1]), "+f"((d)[2]), "+f"((d)[3]) \
                 : "r"((a)[0]), "r"((a)[1]), "r"((a)[2]), "r"((a)[3]), \
                   "r"((b)[0]), "r"((b)[1]))

// ============================================================================
// split: fp32 -> (hi, lo) bf16
// ============================================================================
__global__ __launch_bounds__(256) void split_bf16(
    const float* __restrict__ a, __nv_bfloat16* __restrict__ hi,
    __nv_bfloat16* __restrict__ lo, int n4)
{
    int i = blockIdx.x * 256 + threadIdx.x;
    int stride = gridDim.x * 256;
    for (; i < n4; i += stride) {
        float4 v = ((const float4*)a)[i];
        __nv_bfloat16 h0 = __float2bfloat16(v.x), h1 = __float2bfloat16(v.y);
        __nv_bfloat16 h2 = __float2bfloat16(v.z), h3 = __float2bfloat16(v.w);
        __nv_bfloat16 l0 = __float2bfloat16(v.x - __bfloat162float(h0));
        __nv_bfloat16 l1 = __float2bfloat16(v.y - __bfloat162float(h1));
        __nv_bfloat16 l2 = __float2bfloat16(v.z - __bfloat162float(h2));
        __nv_bfloat16 l3 = __float2bfloat16(v.w - __bfloat162float(h3));
        uint32_t ph0 = ((uint32_t)__bfloat16_as_ushort(h1) << 16) | __bfloat16_as_ushort(h0);
        uint32_t ph1 = ((uint32_t)__bfloat16_as_ushort(h3) << 16) | __bfloat16_as_ushort(h2);
        uint32_t pl0 = ((uint32_t)__bfloat16_as_ushort(l1) << 16) | __bfloat16_as_ushort(l0);
        uint32_t pl1 = ((uint32_t)__bfloat16_as_ushort(l3) << 16) | __bfloat16_as_ushort(l2);
        ((uint2*)hi)[i] = make_uint2(ph0, ph1);
        ((uint2*)lo)[i] = make_uint2(pl0, pl1);
    }
}

// ============================================================================
// transpose + split: W[K,N] fp32 -> Wt_hi/lo[N,K] bf16
// ============================================================================
__global__ __launch_bounds__(256) void transpose_split(
    const float* __restrict__ W, __nv_bfloat16* __restrict__ thi,
    __nv_bfloat16* __restrict__ tlo, int K, int N)
{
    __shared__ float tile[32][33];
    int n0 = blockIdx.x * 32, k0 = blockIdx.y * 32;
    int tx = threadIdx.x, ty = threadIdx.y;  // 32 x 8
#pragma unroll
    for (int i = 0; i < 4; i++)
        tile[ty + 8 * i][tx] = W[(size_t)(k0 + ty + 8 * i) * N + n0 + tx];
    __syncthreads();
#pragma unroll
    for (int i = 0; i < 4; i++) {
        float v = tile[tx][ty + 8 * i];
        __nv_bfloat16 h = __float2bfloat16(v);
        __nv_bfloat16 l = __float2bfloat16(v - __bfloat162float(h));
        size_t o = (size_t)(n0 + ty + 8 * i) * K + k0 + tx;
        thi[o] = h;
        tlo[o] = l;
    }
}

// ============================================================================
// mma.sync split-bf16 GEMM: C[M,N] = A[M,K] @ Wt[N,K]^T + bias (opt. SiLU)
// 128x128 tile, BLK_K=32, 256 threads = 8 warps (4m x 2n), warp tile 32x64.
// 3 MMAs per (m,n,k16): Ahi*Bhi + Ahi*Blo + Alo*Bhi, fp32 accumulate.
// cp.async double-buffered SMEM; rows padded to 40 bf16 (80B) for ldmatrix.
// Each thread copies 32B per array (2 x cp.async 16B): row = t>>1, half = t&1.
// SMEM per buffer: Ahi|Alo|Bhi|Blo each 128x40 bf16 = 10240B -> 40960B.
// ============================================================================
#define GPAD 40
#define GARR (128 * GPAD * 2)            // bytes per array (10240)
#define GBUF (4 * GARR)                  // bytes per buffer (40960)
#define GSMEM (2 * GBUF)                 // 81920

template <bool SILU>
__global__ __launch_bounds__(256) void gemm_mma_bf16x3(
    const __nv_bfloat16* __restrict__ Ahi, const __nv_bfloat16* __restrict__ Alo,
    const __nv_bfloat16* __restrict__ Bhi, const __nv_bfloat16* __restrict__ Blo,
    const float* __restrict__ bias, float* __restrict__ C,
    int M, int N, int K)
{
    extern __shared__ __align__(128) char smem[];
    const uint32_t sb = smem_u32(smem);
    const int t = threadIdx.x, lane = t & 31, wid = t >> 5;
    const int wm = (wid & 3) * 32;        // warp m offset in tile
    const int wn = (wid >> 2) * 64;       // warp n offset in tile
    const int tm = blockIdx.y * 128, tn = blockIdx.x * 128;
    const int NC = K >> 5;                // K / 32

    // ---- cp.async mapping: row = t>>1, 16-element (32B) half = t&1 ----
    const int grow = t >> 1, ghalf = t & 1;
    const __nv_bfloat16* gsrc[4] = {
        Ahi + (size_t)(tm + grow) * K + ghalf * 16,
        Alo + (size_t)(tm + grow) * K + ghalf * 16,
        Bhi + (size_t)(tn + grow) * K + ghalf * 16,
        Blo + (size_t)(tn + grow) * K + ghalf * 16 };
    const uint32_t sdst = sb + (uint32_t)grow * (GPAD * 2) + (uint32_t)ghalf * 32;

    // ---- ldmatrix lane addresses (byte offsets within an array) ----
    // A (m16k16 x4): rows wm+(lane&15), col half (lane>>4)*8 elems
    const uint32_t a_lane = (uint32_t)(wm + (lane & 15)) * (GPAD * 2) + (uint32_t)(lane >> 4) * 16;
    // B pair-of-ntiles x4: lanes 0-7: (nt0,k0-7); 8-15: (nt0,k8-15); 16-23: (nt1,k0-7); 24-31: (nt1,k8-15)
    const uint32_t b_lane = (uint32_t)(wn + ((lane >> 4) & 1) * 8 + (lane & 7)) * (GPAD * 2)
                          + (uint32_t)((lane >> 3) & 1) * 16;

    float acc[2][8][4];
#pragma unroll
    for (int i = 0; i < 2; i++)
#pragma unroll
        for (int j = 0; j < 8; j++)
#pragma unroll
            for (int c = 0; c < 4; c++) acc[i][j][c] = 0.0f;

    // ---- prologue: load buffer 0 (full 32B per thread per array) ----
#pragma unroll
    for (int a = 0; a < 4; a++) {
        CP_ASYNC16(sdst + a * GARR,      gsrc[a]);
        CP_ASYNC16(sdst + a * GARR + 16, gsrc[a] + 8);
    }
    CP_COMMIT();

    for (int c = 0; c < NC; c++) {
        if (c + 1 < NC) {
            uint32_t dst = sdst + ((c + 1) & 1) * GBUF;
#pragma unroll
            for (int a = 0; a < 4; a++) {
                const __nv_bfloat16* s = gsrc[a] + (size_t)(c + 1) * 32;
                CP_ASYNC16(dst + a * GARR,      s);
                CP_ASYNC16(dst + a * GARR + 16, s + 8);
            }
            CP_COMMIT();
            CP_WAIT(1);
        } else {
            CP_WAIT(0);
        }
        __syncthreads();

        const uint32_t bufb = sb + (c & 1) * GBUF;
        const uint32_t sAh = bufb + a_lane, sAl = bufb + GARR + a_lane;
        const uint32_t sBh = bufb + 2 * GARR + b_lane, sBl = bufb + 3 * GARR + b_lane;

#pragma unroll
        for (int ks = 0; ks < 2; ks++) {
            uint32_t ah[2][4], al[2][4], bh[8][2], bl[8][2];
#pragma unroll
            for (int i = 0; i < 2; i++) {
                LDSM4(ah[i][0], ah[i][1], ah[i][2], ah[i][3], sAh + i * 16 * (GPAD * 2) + ks * 32);
                LDSM4(al[i][0], al[i][1], al[i][2], al[i][3], sAl + i * 16 * (GPAD * 2) + ks * 32);
            }
#pragma unroll
            for (int jj = 0; jj < 4; jj++) {
                uint32_t r0, r1, r2, r3;
                LDSM4(r0, r1, r2, r3, sBh + jj * 16 * (GPAD * 2) + ks * 32);
                bh[jj * 2][0] = r0; bh[jj * 2][1] = r1;
                bh[jj * 2 + 1][0] = r2; bh[jj * 2 + 1][1] = r3;
                LDSM4(r0, r1, r2, r3, sBl + jj * 16 * (GPAD * 2) + ks * 32);
                bl[jj * 2][0] = r0; bl[jj * 2][1] = r1;
                bl[jj * 2 + 1][0] = r2; bl[jj * 2 + 1][1] = r3;
            }
#pragma unroll
            for (int i = 0; i < 2; i++)
#pragma unroll
                for (int j = 0; j < 8; j++) {
                    MMA16816(acc[i][j], ah[i], bh[j]);
                    MMA16816(acc[i][j], ah[i], bl[j]);
                    MMA16816(acc[i][j], al[i], bh[j]);
                }
        }
        __syncthreads();
    }

    // ---- epilogue ----
    const int quad = lane >> 2, pair = lane & 3;
#pragma unroll
    for (int i = 0; i < 2; i++) {
        int row0 = tm + wm + i * 16 + quad;
#pragma unroll
        for (int j = 0; j < 8; j++) {
            int col = tn + wn + j * 8 + pair * 2;
            float b0 = bias[col], b1 = bias[col + 1];
            float v0 = acc[i][j][0] + b0, v1 = acc[i][j][1] + b1;
            float v2 = acc[i][j][2] + b0, v3 = acc[i][j][3] + b1;
            if (SILU) {
                v0 = v0 / (1.0f + __expf(-v0));
                v1 = v1 / (1.0f + __expf(-v1));
                v2 = v2 / (1.0f + __expf(-v2));
                v3 = v3 / (1.0f + __expf(-v3));
            }
            *(float2*)(C + (size_t)row0 * N + col)       = make_float2(v0, v1);
            *(float2*)(C + (size_t)(row0 + 8) * N + col) = make_float2(v2, v3);
        }
    }
}

// ============================================================================
// RoPE + head scatter (known-good R1 kernel)
// ============================================================================
__global__ __launch_bounds__(256) void rope_scatter(
    const float* __restrict__ qkv,
    const float* __restrict__ cosT, const float* __restrict__ sinT,
    float* __restrict__ Q, float* __restrict__ Kv, float* __restrict__ V)
{
    const int bl = blockIdx.x;
    const int b = bl >> 11, l = bl & 2047;
    const float* row = qkv + (size_t)bl * (3 * HDIM);
    const float* cr = cosT + (size_t)l * (HDIM / 2);
    const float* sr = sinT + (size_t)l * (HDIM / 2);

    __shared__ float buf[NHEADS * 132];
    const int warp = threadIdx.x >> 5, lane = threadIdx.x & 31;

    for (int i = threadIdx.x; i < HDIM / 2; i += 256) {
        float u1 = row[i], u2 = row[i + HDIM / 2];
        float c = cr[i], s = sr[i];
        int h = i & 15, d = i >> 4;
        buf[h * 132 + d]      = u1 * c + u2 * s;
        buf[h * 132 + d + 64] = -u1 * s + u2 * c;
    }
    __syncthreads();
    for (int h = warp * 2; h < warp * 2 + 2; h++) {
        float* dst = Q + ((size_t)(b * NHEADS + h) * LSEQ + l) * HD;
        for (int d = lane; d < HD; d += 32) dst[d] = buf[h * 132 + d];
    }
    __syncthreads();

    for (int i = threadIdx.x; i < HDIM / 2; i += 256) {
        float u1 = row[HDIM + i], u2 = row[HDIM + i + HDIM / 2];
        float c = cr[i], s = sr[i];
        int h = i & 15, d = i >> 4;
        buf[h * 132 + d]      = u1 * c + u2 * s;
        buf[h * 132 + d + 64] = -u1 * s + u2 * c;
    }
    __syncthreads();
    for (int h = warp * 2; h < warp * 2 + 2; h++) {
        float* dst = Kv + ((size_t)(b * NHEADS + h) * LSEQ + l) * HD;
        for (int d = lane; d < HD; d += 32) dst[d] = buf[h * 132 + d];
    }
    __syncthreads();

    for (int i = threadIdx.x; i < HDIM; i += 256) {
        int h = i & 15, d = i >> 4;
        buf[h * 132 + d] = row[2 * HDIM + i];
    }
    __syncthreads();
    for (int h = warp * 2; h < warp * 2 + 2; h++) {
        float* dst = V + ((size_t)(b * NHEADS + h) * LSEQ + l) * HD;
        for (int d = lane; d < HD; d += 32) dst[d] = buf[h * 132 + d];
    }
}

// ============================================================================
// Flash attention (causal), fp32 (known-good R1 kernel)
// ============================================================================
#define BM 64
#define BN 64
__global__ __launch_bounds__(256) void flash_attn(
    const float* __restrict__ Q, const float* __restrict__ K,
    const float* __restrict__ V, float* __restrict__ Y)
{
    extern __shared__ float sm[];
    float (*Qs)[132] = (float(*)[132])sm;
    float (*Ks)[132] = (float(*)[132])(sm + 64 * 132);
    float (*Vs)[132] = (float(*)[132])(sm + 2 * 64 * 132);
    float (*Ps)[65]  = (float(*)[65])(sm + 3 * 64 * 132);

    const int qb = blockIdx.x, bh = blockIdx.y;
    const int b = bh >> 4, h = bh & 15;
    const size_t base = (size_t)bh * LSEQ * HD;
    const int t = threadIdx.x, tx = t & 15, ty = t >> 4;
    const float scale = 0.08838834764831845f;

    {
        const float* Qg = Q + base + (size_t)qb * BM * HD;
        for (int f = t; f < BM * HD / 4; f += 256) {
            int pos = f * 4, r = pos >> 7, d = pos & 127;
            *(float4*)&Qs[r][d] = *(const float4*)&Qg[pos];
        }
    }

    float acc[4][8];
#pragma unroll
    for (int i = 0; i < 4; i++)
#pragma unroll
        for (int j = 0; j < 8; j++) acc[i][j] = 0.0f;
    float mi[4], li[4];
#pragma unroll
    for (int i = 0; i < 4; i++) { mi[i] = -1e30f; li[i] = 0.0f; }

    for (int kb = 0; kb <= qb; kb++) {
        __syncthreads();
        {
            const float* Kg = K + base + (size_t)kb * BN * HD;
            const float* Vg = V + base + (size_t)kb * BN * HD;
            for (int f = t; f < BN * HD / 4; f += 256) {
                int pos = f * 4, r = pos >> 7, d = pos & 127;
                *(float4*)&Ks[r][d] = *(const float4*)&Kg[pos];
                *(float4*)&Vs[r][d] = *(const float4*)&Vg[pos];
            }
        }
        __syncthreads();

        float s[4][4];
#pragma unroll
        for (int i = 0; i < 4; i++)
#pragma unroll
            for (int j = 0; j < 4; j++) s[i][j] = 0.0f;

#pragma unroll 4
        for (int kk = 0; kk < HD; kk++) {
            float ra[4], rbv[4];
#pragma unroll
            for (int i = 0; i < 4; i++) ra[i] = Qs[ty + i * 16][kk];
#pragma unroll
            for (int j = 0; j < 4; j++) rbv[j] = Ks[tx + j * 16][kk];
#pragma unroll
            for (int i = 0; i < 4; i++)
#pragma unroll
                for (int j = 0; j < 4; j++) s[i][j] += ra[i] * rbv[j];
        }

#pragma unroll
        for (int i = 0; i < 4; i++)
#pragma unroll
            for (int j = 0; j < 4; j++) s[i][j] *= scale;

        if (kb == qb) {
#pragma unroll
            for (int i = 0; i < 4; i++)
#pragma unroll
                for (int j = 0; j < 4; j++)
                    if (tx + j * 16 > ty + i * 16) s[i][j] = -1e30f;
        }

#pragma unroll
        for (int i = 0; i < 4; i++) {
            float v = fmaxf(fmaxf(s[i][0], s[i][1]), fmaxf(s[i][2], s[i][3]));
#pragma unroll
            for (int off = 8; off >= 1; off >>= 1)
                v = fmaxf(v, __shfl_xor_sync(0xffffffffu, v, off));
            float mnew = fmaxf(mi[i], v);
            float alpha = __expf(mi[i] - mnew);
            float sum = 0.0f;
#pragma unroll
            for (int j = 0; j < 4; j++) {
                float p = __expf(s[i][j] - mnew);
                Ps[ty + i * 16][tx + j * 16] = p;
                sum += p;
            }
#pragma unroll
            for (int off = 8; off >= 1; off >>= 1)
                sum += __shfl_xor_sync(0xffffffffu, sum, off);
            li[i] = li[i] * alpha + sum;
            mi[i] = mnew;
#pragma unroll
            for (int j = 0; j < 8; j++) acc[i][j] *= alpha;
        }
        __syncthreads();

#pragma unroll 4
        for (int kk = 0; kk < BN; kk++) {
            float pv[4], vv[8];
#pragma unroll
            for (int i = 0; i < 4; i++) pv[i] = Ps[ty + i * 16][kk];
#pragma unroll
            for (int j = 0; j < 8; j++) vv[j] = Vs[kk][tx + j * 16];
#pragma unroll
            for (int i = 0; i < 4; i++)
#pragma unroll
                for (int j = 0; j < 8; j++) acc[i][j] += pv[i] * vv[j];
        }
    }

#pragma unroll
    for (int i = 0; i < 4; i++) {
        int l = qb * BM + ty + i * 16;
        float inv = 1.0f / li[i];
        float* dst = Y + (size_t)(b * LSEQ + l) * HDIM + h * HD;
#pragma unroll
        for (int j = 0; j < 8; j++) dst[tx + j * 16] = acc[i][j] * inv;
    }
}

// ============================================================================
// launch
// ============================================================================
extern "C" void kernel_launch(void* const* d_in, const int* in_sizes, int n_in,
                              void* d_out, int out_size)
{
    const float* x    = (const float*)d_in[0];
    const float* Wqkv = (const float*)d_in[1];
    const float* bqkv = (const float*)d_in[2];
    const float* Wfc2 = (const float*)d_in[3];
    const float* bfc2 = (const float*)d_in[4];
    const float* cosT = (const float*)d_in[5];
    const float* sinT = (const float*)d_in[6];
    float* out = (float*)d_out;

    float *qkv, *q, *k, *v, *y;
    __nv_bfloat16 *xhi, *xlo, *yhi, *ylo, *w1hi, *w1lo, *w2hi, *w2lo;
    cudaGetSymbolAddress((void**)&qkv, g_qkv);
    cudaGetSymbolAddress((void**)&q, g_q);
    cudaGetSymbolAddress((void**)&k, g_k);
    cudaGetSymbolAddress((void**)&v, g_v);
    cudaGetSymbolAddress((void**)&y, g_y);
    cudaGetSymbolAddress((void**)&xhi, g_xhi);
    cudaGetSymbolAddress((void**)&xlo, g_xlo);
    cudaGetSymbolAddress((void**)&yhi, g_yhi);
    cudaGetSymbolAddress((void**)&ylo, g_ylo);
    cudaGetSymbolAddress((void**)&w1hi, g_w1hi);
    cudaGetSymbolAddress((void**)&w1lo, g_w1lo);
    cudaGetSymbolAddress((void**)&w2hi, g_w2hi);
    cudaGetSymbolAddress((void**)&w2lo, g_w2lo);

    const int M = BATCH * LSEQ;  // 8192

    static bool attr_done = false;
    if (!attr_done) {
        cudaFuncSetAttribute(gemm_mma_bf16x3<false>, cudaFuncAttributeMaxDynamicSharedMemorySize, GSMEM);
        cudaFuncSetAttribute(gemm_mma_bf16x3<true>,  cudaFuncAttributeMaxDynamicSharedMemorySize, GSMEM);
        int fa_smem = (3 * 64 * 132 + 64 * 65) * (int)sizeof(float);
        cudaFuncSetAttribute(flash_attn, cudaFuncAttributeMaxDynamicSharedMemorySize, fa_smem);
        attr_done = true;
    }

    // 0) prep: split x, transpose+split weights
    split_bf16<<<1024, 256>>>(x, xhi, xlo, M * HDIM / 4);
    transpose_split<<<dim3(3 * HDIM / 32, HDIM / 32), dim3(32, 8)>>>(Wqkv, w1hi, w1lo, HDIM, 3 * HDIM);
    transpose_split<<<dim3(HDIM / 32, HDIM / 32), dim3(32, 8)>>>(Wfc2, w2hi, w2lo, HDIM, HDIM);

    // 1) qkv = x @ Wqkv + bqkv   (tensor-core split-bf16, mma.sync)
    gemm_mma_bf16x3<false><<<dim3(3 * HDIM / 128, M / 128), 256, GSMEM>>>(
        xhi, xlo, w1hi, w1lo, bqkv, qkv, M, 3 * HDIM, HDIM);

    // 2) RoPE + head scatter
    rope_scatter<<<M, 256>>>(qkv, cosT, sinT, q, k, v);

    // 3) causal flash attention (fp32)
    int fa_smem = (3 * 64 * 132 + 64 * 65) * (int)sizeof(float);
    flash_attn<<<dim3(LSEQ / BM, BATCH * NHEADS), 256, fa_smem>>>(q, k, v, y);

    // 4) out = silu(y @ Wfc2 + bfc2)
    split_bf16<<<1024, 256>>>(y, yhi, ylo, M * HDIM / 4);
    gemm_mma_bf16x3<true><<<dim3(HDIM / 128, M / 128), 256, GSMEM>>>(
        yhi, ylo, w2hi, w2lo, bfc2, out, M, HDIM, HDIM);
}

// round 13
// speedup vs baseline: 2.6509x; 1.6992x over previous
#include <cuda_runtime.h>
#include <cuda_bf16.h>
#include <stdint.h>
#include <math.h>

#define BATCH 4
#define LSEQ  2048
#define HDIM  2048
#define NHEADS 16
#define HD    128

// ---------------- scratch (no allocations allowed) ----------------
__device__ __align__(16) float g_qkv[(size_t)BATCH * LSEQ * 3 * HDIM];   // (B*L, 3H)

// bf16 split operands
__device__ __align__(16) __nv_bfloat16 g_xhi[(size_t)BATCH * LSEQ * HDIM];
__device__ __align__(16) __nv_bfloat16 g_xlo[(size_t)BATCH * LSEQ * HDIM];
__device__ __align__(16) __nv_bfloat16 g_yhi[(size_t)BATCH * LSEQ * HDIM];
__device__ __align__(16) __nv_bfloat16 g_ylo[(size_t)BATCH * LSEQ * HDIM];
__device__ __align__(16) __nv_bfloat16 g_w1hi[(size_t)3 * HDIM * HDIM];  // [6144,2048] (N,K)
__device__ __align__(16) __nv_bfloat16 g_w1lo[(size_t)3 * HDIM * HDIM];
__device__ __align__(16) __nv_bfloat16 g_w2hi[(size_t)HDIM * HDIM];
__device__ __align__(16) __nv_bfloat16 g_w2lo[(size_t)HDIM * HDIM];

// attention operands, (b,h,l,d) bf16 hi/lo (scale folded into q)
#define AQN ((size_t)BATCH * NHEADS * LSEQ * HD)
__device__ __align__(16) __nv_bfloat16 g_qhi[AQN];
__device__ __align__(16) __nv_bfloat16 g_qlo[AQN];
__device__ __align__(16) __nv_bfloat16 g_khi[AQN];
__device__ __align__(16) __nv_bfloat16 g_klo[AQN];
__device__ __align__(16) __nv_bfloat16 g_vhi[AQN];
__device__ __align__(16) __nv_bfloat16 g_vlo[AQN];

// ---------------- helpers ----------------
__device__ __forceinline__ uint32_t smem_u32(const void* p) {
    uint32_t a;
    asm("{ .reg .u64 t; cvta.to.shared.u64 t, %1; cvt.u32.u64 %0, t; }" : "=r"(a) : "l"(p));
    return a;
}
#define CP_ASYNC16(dst, src) \
    asm volatile("cp.async.cg.shared.global [%0], [%1], 16;" :: "r"(dst), "l"(src))
#define CP_COMMIT() asm volatile("cp.async.commit_group;" ::: "memory")
#define CP_WAIT(n)  asm volatile("cp.async.wait_group %0;" :: "n"(n) : "memory")

#define LDSM4(r0, r1, r2, r3, addr) \
    asm volatile("ldmatrix.sync.aligned.m8n8.x4.shared.b16 {%0,%1,%2,%3}, [%4];" \
                 : "=r"(r0), "=r"(r1), "=r"(r2), "=r"(r3) : "r"(addr))
#define LDSM4T(r0, r1, r2, r3, addr) \
    asm volatile("ldmatrix.sync.aligned.m8n8.x4.trans.shared.b16 {%0,%1,%2,%3}, [%4];" \
                 : "=r"(r0), "=r"(r1), "=r"(r2), "=r"(r3) : "r"(addr))

#define MMA16816(d, a, b) \
    asm volatile("mma.sync.aligned.m16n8k16.row.col.f32.bf16.bf16.f32 " \
                 "{%0,%1,%2,%3}, {%4,%5,%6,%7}, {%8,%9}, {%0,%1,%2,%3};" \
                 : "+f"((d)[0]), "+f"((d)[1]), "+f"((d)[2]), "+f"((d)[3]) \
                 : "r"((a)[0]), "r"((a)[1]), "r"((a)[2]), "r"((a)[3]), \
                   "r"((b)[0]), "r"((b)[1]))

__device__ __forceinline__ uint32_t pack_bf2(float x, float y) {
    __nv_bfloat16 hx = __float2bfloat16(x), hy = __float2bfloat16(y);
    return ((uint32_t)__bfloat16_as_ushort(hy) << 16) | __bfloat16_as_ushort(hx);
}

// ============================================================================
// split: fp32 -> (hi, lo) bf16
// ============================================================================
__global__ __launch_bounds__(256) void split_bf16(
    const float* __restrict__ a, __nv_bfloat16* __restrict__ hi,
    __nv_bfloat16* __restrict__ lo, int n4)
{
    int i = blockIdx.x * 256 + threadIdx.x;
    int stride = gridDim.x * 256;
    for (; i < n4; i += stride) {
        float4 v = ((const float4*)a)[i];
        __nv_bfloat16 h0 = __float2bfloat16(v.x), h1 = __float2bfloat16(v.y);
        __nv_bfloat16 h2 = __float2bfloat16(v.z), h3 = __float2bfloat16(v.w);
        __nv_bfloat16 l0 = __float2bfloat16(v.x - __bfloat162float(h0));
        __nv_bfloat16 l1 = __float2bfloat16(v.y - __bfloat162float(h1));
        __nv_bfloat16 l2 = __float2bfloat16(v.z - __bfloat162float(h2));
        __nv_bfloat16 l3 = __float2bfloat16(v.w - __bfloat162float(h3));
        uint32_t ph0 = ((uint32_t)__bfloat16_as_ushort(h1) << 16) | __bfloat16_as_ushort(h0);
        uint32_t ph1 = ((uint32_t)__bfloat16_as_ushort(h3) << 16) | __bfloat16_as_ushort(h2);
        uint32_t pl0 = ((uint32_t)__bfloat16_as_ushort(l1) << 16) | __bfloat16_as_ushort(l0);
        uint32_t pl1 = ((uint32_t)__bfloat16_as_ushort(l3) << 16) | __bfloat16_as_ushort(l2);
        ((uint2*)hi)[i] = make_uint2(ph0, ph1);
        ((uint2*)lo)[i] = make_uint2(pl0, pl1);
    }
}

// ============================================================================
// transpose + split: W[K,N] fp32 -> Wt_hi/lo[N,K] bf16
// ============================================================================
__global__ __launch_bounds__(256) void transpose_split(
    const float* __restrict__ W, __nv_bfloat16* __restrict__ thi,
    __nv_bfloat16* __restrict__ tlo, int K, int N)
{
    __shared__ float tile[32][33];
    int n0 = blockIdx.x * 32, k0 = blockIdx.y * 32;
    int tx = threadIdx.x, ty = threadIdx.y;  // 32 x 8
#pragma unroll
    for (int i = 0; i < 4; i++)
        tile[ty + 8 * i][tx] = W[(size_t)(k0 + ty + 8 * i) * N + n0 + tx];
    __syncthreads();
#pragma unroll
    for (int i = 0; i < 4; i++) {
        float v = tile[tx][ty + 8 * i];
        __nv_bfloat16 h = __float2bfloat16(v);
        __nv_bfloat16 l = __float2bfloat16(v - __bfloat162float(h));
        size_t o = (size_t)(n0 + ty + 8 * i) * K + k0 + tx;
        thi[o] = h;
        tlo[o] = l;
    }
}

// ============================================================================
// mma.sync split-bf16 GEMM (as R10, restructured for 2 CTAs/SM)
// ============================================================================
#define GPAD 40
#define GROW (GPAD * 2)                  // 80B row stride
#define GARR (128 * GROW)                // bytes per array (10240)
#define GBUF (4 * GARR)                  // bytes per buffer (40960)
#define GSMEM (2 * GBUF)                 // 81920

template <bool SILU>
__global__ __launch_bounds__(256, 2) void gemm_mma_bf16x3(
    const __nv_bfloat16* __restrict__ Ahi, const __nv_bfloat16* __restrict__ Alo,
    const __nv_bfloat16* __restrict__ Bhi, const __nv_bfloat16* __restrict__ Blo,
    const float* __restrict__ bias, float* __restrict__ C,
    int M, int N, int K)
{
    extern __shared__ __align__(128) char smem[];
    const uint32_t sb = smem_u32(smem);
    const int t = threadIdx.x, lane = t & 31, wid = t >> 5;
    const int wm = (wid & 3) * 32;
    const int wn = (wid >> 2) * 64;
    const int tm = blockIdx.y * 128, tn = blockIdx.x * 128;
    const int NC = K >> 5;

    const int grow = t >> 1, ghalf = t & 1;
    const __nv_bfloat16* gsrc[4] = {
        Ahi + (size_t)(tm + grow) * K + ghalf * 16,
        Alo + (size_t)(tm + grow) * K + ghalf * 16,
        Bhi + (size_t)(tn + grow) * K + ghalf * 16,
        Blo + (size_t)(tn + grow) * K + ghalf * 16 };
    const uint32_t sdst = sb + (uint32_t)grow * GROW + (uint32_t)ghalf * 32;

    const uint32_t a_lane = (uint32_t)(wm + (lane & 15)) * GROW + (uint32_t)(lane >> 4) * 16;
    const uint32_t b_lane = (uint32_t)(wn + ((lane >> 4) & 1) * 8 + (lane & 7)) * GROW
                          + (uint32_t)((lane >> 3) & 1) * 16;

    float acc[2][8][4];
#pragma unroll
    for (int i = 0; i < 2; i++)
#pragma unroll
        for (int j = 0; j < 8; j++)
#pragma unroll
            for (int c = 0; c < 4; c++) acc[i][j][c] = 0.0f;

#pragma unroll
    for (int a = 0; a < 4; a++) {
        CP_ASYNC16(sdst + a * GARR,      gsrc[a]);
        CP_ASYNC16(sdst + a * GARR + 16, gsrc[a] + 8);
    }
    CP_COMMIT();

    for (int c = 0; c < NC; c++) {
        if (c + 1 < NC) {
            uint32_t dst = sdst + ((c + 1) & 1) * GBUF;
#pragma unroll
            for (int a = 0; a < 4; a++) {
                const __nv_bfloat16* s = gsrc[a] + (size_t)(c + 1) * 32;
                CP_ASYNC16(dst + a * GARR,      s);
                CP_ASYNC16(dst + a * GARR + 16, s + 8);
            }
            CP_COMMIT();
            CP_WAIT(1);
        } else {
            CP_WAIT(0);
        }
        __syncthreads();

        const uint32_t bufb = sb + (c & 1) * GBUF;
        const uint32_t sAh = bufb + a_lane, sAl = bufb + GARR + a_lane;
        const uint32_t sBh = bufb + 2 * GARR + b_lane, sBl = bufb + 3 * GARR + b_lane;

#pragma unroll
        for (int ks = 0; ks < 2; ks++) {
            uint32_t ah[2][4], al[2][4];
#pragma unroll
            for (int i = 0; i < 2; i++) {
                LDSM4(ah[i][0], ah[i][1], ah[i][2], ah[i][3], sAh + i * 16 * GROW + ks * 32);
                LDSM4(al[i][0], al[i][1], al[i][2], al[i][3], sAl + i * 16 * GROW + ks * 32);
            }
#pragma unroll
            for (int jj = 0; jj < 4; jj++) {
                uint32_t h0, h1, h2, h3, l0, l1, l2, l3;
                LDSM4(h0, h1, h2, h3, sBh + jj * 16 * GROW + ks * 32);
                LDSM4(l0, l1, l2, l3, sBl + jj * 16 * GROW + ks * 32);
                uint32_t bh0[2] = {h0, h1}, bh1[2] = {h2, h3};
                uint32_t bl0[2] = {l0, l1}, bl1[2] = {l2, l3};
#pragma unroll
                for (int i = 0; i < 2; i++) {
                    MMA16816(acc[i][jj * 2],     ah[i], bh0);
                    MMA16816(acc[i][jj * 2],     ah[i], bl0);
                    MMA16816(acc[i][jj * 2],     al[i], bh0);
                    MMA16816(acc[i][jj * 2 + 1], ah[i], bh1);
                    MMA16816(acc[i][jj * 2 + 1], ah[i], bl1);
                    MMA16816(acc[i][jj * 2 + 1], al[i], bh1);
                }
            }
        }
        __syncthreads();
    }

    const int quad = lane >> 2, pair = lane & 3;
#pragma unroll
    for (int i = 0; i < 2; i++) {
        int row0 = tm + wm + i * 16 + quad;
#pragma unroll
        for (int j = 0; j < 8; j++) {
            int col = tn + wn + j * 8 + pair * 2;
            float b0 = bias[col], b1 = bias[col + 1];
            float v0 = acc[i][j][0] + b0, v1 = acc[i][j][1] + b1;
            float v2 = acc[i][j][2] + b0, v3 = acc[i][j][3] + b1;
            if (SILU) {
                v0 = v0 / (1.0f + __expf(-v0));
                v1 = v1 / (1.0f + __expf(-v1));
                v2 = v2 / (1.0f + __expf(-v2));
                v3 = v3 / (1.0f + __expf(-v3));
            }
            *(float2*)(C + (size_t)row0 * N + col)       = make_float2(v0, v1);
            *(float2*)(C + (size_t)(row0 + 8) * N + col) = make_float2(v2, v3);
        }
    }
}

// ============================================================================
// RoPE + head scatter -> bf16 hi/lo (scale folded into q)
// ============================================================================
__global__ __launch_bounds__(256) void rope_scatter(
    const float* __restrict__ qkv,
    const float* __restrict__ cosT, const float* __restrict__ sinT,
    __nv_bfloat16* __restrict__ Qh, __nv_bfloat16* __restrict__ Ql,
    __nv_bfloat16* __restrict__ Kh, __nv_bfloat16* __restrict__ Kl,
    __nv_bfloat16* __restrict__ Vh, __nv_bfloat16* __restrict__ Vl)
{
    const int bl = blockIdx.x;
    const int b = bl >> 11, l = bl & 2047;
    const float* row = qkv + (size_t)bl * (3 * HDIM);
    const float* cr = cosT + (size_t)l * (HDIM / 2);
    const float* sr = sinT + (size_t)l * (HDIM / 2);
    const float SC = 0.08838834764831845f;  // 1/sqrt(128)

    __shared__ float buf[NHEADS * 132];
    const int warp = threadIdx.x >> 5, lane = threadIdx.x & 31;

    // ---- Q (rotary, scaled) ----
    for (int i = threadIdx.x; i < HDIM / 2; i += 256) {
        float u1 = row[i], u2 = row[i + HDIM / 2];
        float c = cr[i], s = sr[i];
        int h = i & 15, d = i >> 4;
        buf[h * 132 + d]      = (u1 * c + u2 * s) * SC;
        buf[h * 132 + d + 64] = (-u1 * s + u2 * c) * SC;
    }
    __syncthreads();
    for (int h = warp * 2; h < warp * 2 + 2; h++) {
        size_t o = ((size_t)(b * NHEADS + h) * LSEQ + l) * HD;
        for (int d = lane; d < HD; d += 32) {
            float v = buf[h * 132 + d];
            __nv_bfloat16 hi = __float2bfloat16(v);
            Qh[o + d] = hi;
            Ql[o + d] = __float2bfloat16(v - __bfloat162float(hi));
        }
    }
    __syncthreads();

    // ---- K (rotary) ----
    for (int i = threadIdx.x; i < HDIM / 2; i += 256) {
        float u1 = row[HDIM + i], u2 = row[HDIM + i + HDIM / 2];
        float c = cr[i], s = sr[i];
        int h = i & 15, d = i >> 4;
        buf[h * 132 + d]      = u1 * c + u2 * s;
        buf[h * 132 + d + 64] = -u1 * s + u2 * c;
    }
    __syncthreads();
    for (int h = warp * 2; h < warp * 2 + 2; h++) {
        size_t o = ((size_t)(b * NHEADS + h) * LSEQ + l) * HD;
        for (int d = lane; d < HD; d += 32) {
            float v = buf[h * 132 + d];
            __nv_bfloat16 hi = __float2bfloat16(v);
            Kh[o + d] = hi;
            Kl[o + d] = __float2bfloat16(v - __bfloat162float(hi));
        }
    }
    __syncthreads();

    // ---- V ----
    for (int i = threadIdx.x; i < HDIM; i += 256) {
        int h = i & 15, d = i >> 4;
        buf[h * 132 + d] = row[2 * HDIM + i];
    }
    __syncthreads();
    for (int h = warp * 2; h < warp * 2 + 2; h++) {
        size_t o = ((size_t)(b * NHEADS + h) * LSEQ + l) * HD;
        for (int d = lane; d < HD; d += 32) {
            float v = buf[h * 132 + d];
            __nv_bfloat16 hi = __float2bfloat16(v);
            Vh[o + d] = hi;
            Vl[o + d] = __float2bfloat16(v - __bfloat162float(hi));
        }
    }
}

// ============================================================================
// Tensor-core flash attention (causal), split-bf16 mma.sync.
// BM=64 per CTA, 128 threads (4 warps, each owns a 16-row band).
// BN=64 KV tiles, single-buffered SMEM with cp.async prefetch issue.
// SMEM arrays (row stride 272B = 17 banks, conflict-free ldmatrix):
//   Qh|Ql|Kh|Kl|Vh|Vl each 64x272B.
// S = Q*K^T: same A/B mapping as the (verified) GEMM. P*V: B frags via
// ldmatrix.x4.trans on V. P split hi/lo from fp32 accums (3-MMA scheme).
// Writes Y split (hi/lo bf16) at (b, l, h*128+d).
// ============================================================================
#define ARS  272
#define AARR (64 * ARS)                 // 17408
#define AQH 0
#define AQL (1 * AARR)
#define AKH (2 * AARR)
#define AKL (3 * AARR)
#define AVH (4 * AARR)
#define AVL (5 * AARR)
#define ASMEM (6 * AARR)                // 104448

__global__ __launch_bounds__(128) void flash_attn_mma(
    const __nv_bfloat16* __restrict__ Qh, const __nv_bfloat16* __restrict__ Ql,
    const __nv_bfloat16* __restrict__ Kh, const __nv_bfloat16* __restrict__ Kl,
    const __nv_bfloat16* __restrict__ Vh, const __nv_bfloat16* __restrict__ Vl,
    __nv_bfloat16* __restrict__ Yhi, __nv_bfloat16* __restrict__ Ylo)
{
    extern __shared__ __align__(128) char smem[];
    const uint32_t sb = smem_u32(smem);
    const int qb = blockIdx.x, bh = blockIdx.y;
    const int b = bh >> 4, h = bh & 15;
    const size_t base = (size_t)bh * LSEQ * HD;
    const int t = threadIdx.x, lane = t & 31, w = t >> 5;
    const int g = lane >> 2, tq = lane & 3;

    // ldmatrix lane addresses (byte offsets within a 64x272 array)
    const uint32_t a_lane = (uint32_t)(w * 16 + (lane & 15)) * ARS + (uint32_t)(lane >> 4) * 16;
    const uint32_t b_lane = (uint32_t)(((lane >> 4) & 1) * 8 + (lane & 7)) * ARS
                          + (uint32_t)((lane >> 3) & 1) * 16;
    const uint32_t vt_lane = (uint32_t)((lane & 7) + ((lane >> 3) & 1) * 8) * ARS
                           + (uint32_t)((lane >> 4) & 1) * 16;

    const char* ksrc[4] = { (const char*)(Kh + base), (const char*)(Kl + base),
                            (const char*)(Vh + base), (const char*)(Vl + base) };
    const uint32_t kdst[4] = { sb + AKH, sb + AKL, sb + AVH, sb + AVL };

    // prologue: Q tile + KV tile 0
    {
        const char* qsrc[2] = { (const char*)(Qh + base) + (size_t)qb * 64 * HD * 2,
                                (const char*)(Ql + base) + (size_t)qb * 64 * HD * 2 };
#pragma unroll
        for (int a = 0; a < 2; a++)
#pragma unroll
            for (int i = 0; i < 8; i++) {
                int chunk = t + i * 128, row = chunk >> 4, off = (chunk & 15) * 16;
                CP_ASYNC16(sb + AQH + a * AARR + row * ARS + off, qsrc[a] + row * 256 + off);
            }
#pragma unroll
        for (int a = 0; a < 4; a++)
#pragma unroll
            for (int i = 0; i < 8; i++) {
                int chunk = t + i * 128, row = chunk >> 4, off = (chunk & 15) * 16;
                CP_ASYNC16(kdst[a] + row * ARS + off, ksrc[a] + row * 256 + off);
            }
        CP_COMMIT();
    }

    float o[16][4];
#pragma unroll
    for (int n = 0; n < 16; n++)
#pragma unroll
        for (int c = 0; c < 4; c++) o[n][c] = 0.0f;
    float m0 = -1e30f, m1 = -1e30f, l0 = 0.0f, l1 = 0.0f;

    for (int kb = 0; kb <= qb; kb++) {
        CP_WAIT(0);
        __syncthreads();

        // ---- S = Q K^T (scale pre-folded into Q) ----
        float s[8][4];
#pragma unroll
        for (int j = 0; j < 8; j++)
#pragma unroll
            for (int c = 0; c < 4; c++) s[j][c] = 0.0f;

#pragma unroll
        for (int k = 0; k < 8; k++) {
            uint32_t ah[4], al[4];
            LDSM4(ah[0], ah[1], ah[2], ah[3], sb + AQH + a_lane + k * 32);
            LDSM4(al[0], al[1], al[2], al[3], sb + AQL + a_lane + k * 32);
#pragma unroll
            for (int jj = 0; jj < 4; jj++) {
                uint32_t h0, h1, h2, h3, q0, q1, q2, q3;
                LDSM4(h0, h1, h2, h3, sb + AKH + b_lane + jj * 16 * ARS + k * 32);
                LDSM4(q0, q1, q2, q3, sb + AKL + b_lane + jj * 16 * ARS + k * 32);
                uint32_t bh0[2] = {h0, h1}, bh1[2] = {h2, h3};
                uint32_t bl0[2] = {q0, q1}, bl1[2] = {q2, q3};
                MMA16816(s[jj * 2],     ah, bh0);
                MMA16816(s[jj * 2],     ah, bl0);
                MMA16816(s[jj * 2],     al, bh0);
                MMA16816(s[jj * 2 + 1], ah, bh1);
                MMA16816(s[jj * 2 + 1], ah, bl1);
                MMA16816(s[jj * 2 + 1], al, bh1);
            }
        }

        // ---- causal mask (diagonal tile only) ----
        if (kb == qb) {
            int r0 = w * 16 + g, r1 = r0 + 8;
#pragma unroll
            for (int j = 0; j < 8; j++) {
                int c0 = j * 8 + tq * 2;
                if (c0 > r0)     s[j][0] = -1e30f;
                if (c0 + 1 > r0) s[j][1] = -1e30f;
                if (c0 > r1)     s[j][2] = -1e30f;
                if (c0 + 1 > r1) s[j][3] = -1e30f;
            }
        }

        // ---- online softmax ----
        float mx0 = -1e30f, mx1 = -1e30f;
#pragma unroll
        for (int j = 0; j < 8; j++) {
            mx0 = fmaxf(mx0, fmaxf(s[j][0], s[j][1]));
            mx1 = fmaxf(mx1, fmaxf(s[j][2], s[j][3]));
        }
        mx0 = fmaxf(mx0, __shfl_xor_sync(0xffffffffu, mx0, 1));
        mx0 = fmaxf(mx0, __shfl_xor_sync(0xffffffffu, mx0, 2));
        mx1 = fmaxf(mx1, __shfl_xor_sync(0xffffffffu, mx1, 1));
        mx1 = fmaxf(mx1, __shfl_xor_sync(0xffffffffu, mx1, 2));
        float mn0 = fmaxf(m0, mx0), mn1 = fmaxf(m1, mx1);
        float al0 = __expf(m0 - mn0), al1 = __expf(m1 - mn1);
        float sum0 = 0.0f, sum1 = 0.0f;
#pragma unroll
        for (int j = 0; j < 8; j++) {
            s[j][0] = __expf(s[j][0] - mn0); sum0 += s[j][0];
            s[j][1] = __expf(s[j][1] - mn0); sum0 += s[j][1];
            s[j][2] = __expf(s[j][2] - mn1); sum1 += s[j][2];
            s[j][3] = __expf(s[j][3] - mn1); sum1 += s[j][3];
        }
        sum0 += __shfl_xor_sync(0xffffffffu, sum0, 1);
        sum0 += __shfl_xor_sync(0xffffffffu, sum0, 2);
        sum1 += __shfl_xor_sync(0xffffffffu, sum1, 1);
        sum1 += __shfl_xor_sync(0xffffffffu, sum1, 2);
        l0 = l0 * al0 + sum0;
        l1 = l1 * al1 + sum1;
        m0 = mn0; m1 = mn1;
#pragma unroll
        for (int n = 0; n < 16; n++) {
            o[n][0] *= al0; o[n][1] *= al0;
            o[n][2] *= al1; o[n][3] *= al1;
        }

        // ---- P -> split-bf16 A fragments ----
        uint32_t pa_h[4][4], pa_l[4][4];
#pragma unroll
        for (int ss = 0; ss < 4; ss++) {
            int j0 = ss * 2, j1 = ss * 2 + 1;
            pa_h[ss][0] = pack_bf2(s[j0][0], s[j0][1]);
            pa_h[ss][1] = pack_bf2(s[j0][2], s[j0][3]);
            pa_h[ss][2] = pack_bf2(s[j1][0], s[j1][1]);
            pa_h[ss][3] = pack_bf2(s[j1][2], s[j1][3]);
            float r00 = s[j0][0] - __bfloat162float(__float2bfloat16(s[j0][0]));
            float r01 = s[j0][1] - __bfloat162float(__float2bfloat16(s[j0][1]));
            float r02 = s[j0][2] - __bfloat162float(__float2bfloat16(s[j0][2]));
            float r03 = s[j0][3] - __bfloat162float(__float2bfloat16(s[j0][3]));
            float r10 = s[j1][0] - __bfloat162float(__float2bfloat16(s[j1][0]));
            float r11 = s[j1][1] - __bfloat162float(__float2bfloat16(s[j1][1]));
            float r12 = s[j1][2] - __bfloat162float(__float2bfloat16(s[j1][2]));
            float r13 = s[j1][3] - __bfloat162float(__float2bfloat16(s[j1][3]));
            pa_l[ss][0] = pack_bf2(r00, r01);
            pa_l[ss][1] = pack_bf2(r02, r03);
            pa_l[ss][2] = pack_bf2(r10, r11);
            pa_l[ss][3] = pack_bf2(r12, r13);
        }

        // ---- O += P V ----
#pragma unroll
        for (int ks = 0; ks < 4; ks++) {
#pragma unroll
            for (int nn = 0; nn < 8; nn++) {
                uint32_t h0, h1, h2, h3, q0, q1, q2, q3;
                LDSM4T(h0, h1, h2, h3, sb + AVH + vt_lane + ks * 16 * ARS + nn * 32);
                LDSM4T(q0, q1, q2, q3, sb + AVL + vt_lane + ks * 16 * ARS + nn * 32);
                uint32_t vh0[2] = {h0, h1}, vh1[2] = {h2, h3};
                uint32_t vl0[2] = {q0, q1}, vl1[2] = {q2, q3};
                MMA16816(o[nn * 2],     pa_h[ks], vh0);
                MMA16816(o[nn * 2],     pa_h[ks], vl0);
                MMA16816(o[nn * 2],     pa_l[ks], vh0);
                MMA16816(o[nn * 2 + 1], pa_h[ks], vh1);
                MMA16816(o[nn * 2 + 1], pa_h[ks], vl1);
                MMA16816(o[nn * 2 + 1], pa_l[ks], vh1);
            }
        }

        __syncthreads();
        if (kb < qb) {
            size_t goff = (size_t)(kb + 1) * 64 * HD * 2;
#pragma unroll
            for (int a = 0; a < 4; a++)
#pragma unroll
                for (int i = 0; i < 8; i++) {
                    int chunk = t + i * 128, row = chunk >> 4, off = (chunk & 15) * 16;
                    CP_ASYNC16(kdst[a] + row * ARS + off, ksrc[a] + goff + row * 256 + off);
                }
            CP_COMMIT();
        }
    }

    // ---- epilogue: Y split at (b, l, h*128 + d) ----
    float inv0 = 1.0f / l0, inv1 = 1.0f / l1;
    int r0 = qb * 64 + w * 16 + g, r1 = r0 + 8;
    uint32_t* yh0 = (uint32_t*)(Yhi + ((size_t)(b * LSEQ + r0)) * HDIM + h * HD);
    uint32_t* yl0 = (uint32_t*)(Ylo + ((size_t)(b * LSEQ + r0)) * HDIM + h * HD);
    uint32_t* yh1 = (uint32_t*)(Yhi + ((size_t)(b * LSEQ + r1)) * HDIM + h * HD);
    uint32_t* yl1 = (uint32_t*)(Ylo + ((size_t)(b * LSEQ + r1)) * HDIM + h * HD);
#pragma unroll
    for (int n = 0; n < 16; n++) {
        int di = (n * 8 + tq * 2) >> 1;  // u32 index
        float v0 = o[n][0] * inv0, v1 = o[n][1] * inv0;
        float v2 = o[n][2] * inv1, v3 = o[n][3] * inv1;
        __nv_bfloat16 h0 = __float2bfloat16(v0), h1b = __float2bfloat16(v1);
        __nv_bfloat16 h2 = __float2bfloat16(v2), h3b = __float2bfloat16(v3);
        yh0[di] = ((uint32_t)__bfloat16_as_ushort(h1b) << 16) | __bfloat16_as_ushort(h0);
        yh1[di] = ((uint32_t)__bfloat16_as_ushort(h3b) << 16) | __bfloat16_as_ushort(h2);
        yl0[di] = pack_bf2(v0 - __bfloat162float(h0), v1 - __bfloat162float(h1b));
        yl1[di] = pack_bf2(v2 - __bfloat162float(h2), v3 - __bfloat162float(h3b));
    }
}

// ============================================================================
// launch
// ============================================================================
extern "C" void kernel_launch(void* const* d_in, const int* in_sizes, int n_in,
                              void* d_out, int out_size)
{
    const float* x    = (const float*)d_in[0];
    const float* Wqkv = (const float*)d_in[1];
    const float* bqkv = (const float*)d_in[2];
    const float* Wfc2 = (const float*)d_in[3];
    const float* bfc2 = (const float*)d_in[4];
    const float* cosT = (const float*)d_in[5];
    const float* sinT = (const float*)d_in[6];
    float* out = (float*)d_out;

    float* qkv;
    __nv_bfloat16 *xhi, *xlo, *yhi, *ylo, *w1hi, *w1lo, *w2hi, *w2lo;
    __nv_bfloat16 *qh, *ql, *kh, *kl, *vh, *vl;
    cudaGetSymbolAddress((void**)&qkv, g_qkv);
    cudaGetSymbolAddress((void**)&xhi, g_xhi);
    cudaGetSymbolAddress((void**)&xlo, g_xlo);
    cudaGetSymbolAddress((void**)&yhi, g_yhi);
    cudaGetSymbolAddress((void**)&ylo, g_ylo);
    cudaGetSymbolAddress((void**)&w1hi, g_w1hi);
    cudaGetSymbolAddress((void**)&w1lo, g_w1lo);
    cudaGetSymbolAddress((void**)&w2hi, g_w2hi);
    cudaGetSymbolAddress((void**)&w2lo, g_w2lo);
    cudaGetSymbolAddress((void**)&qh, g_qhi);
    cudaGetSymbolAddress((void**)&ql, g_qlo);
    cudaGetSymbolAddress((void**)&kh, g_khi);
    cudaGetSymbolAddress((void**)&kl, g_klo);
    cudaGetSymbolAddress((void**)&vh, g_vhi);
    cudaGetSymbolAddress((void**)&vl, g_vlo);

    const int M = BATCH * LSEQ;  // 8192

    static bool attr_done = false;
    if (!attr_done) {
        cudaFuncSetAttribute(gemm_mma_bf16x3<false>, cudaFuncAttributeMaxDynamicSharedMemorySize, GSMEM);
        cudaFuncSetAttribute(gemm_mma_bf16x3<true>,  cudaFuncAttributeMaxDynamicSharedMemorySize, GSMEM);
        cudaFuncSetAttribute(flash_attn_mma, cudaFuncAttributeMaxDynamicSharedMemorySize, ASMEM);
        attr_done = true;
    }

    // 0) prep: split x, transpose+split weights
    split_bf16<<<1024, 256>>>(x, xhi, xlo, M * HDIM / 4);
    transpose_split<<<dim3(3 * HDIM / 32, HDIM / 32), dim3(32, 8)>>>(Wqkv, w1hi, w1lo, HDIM, 3 * HDIM);
    transpose_split<<<dim3(HDIM / 32, HDIM / 32), dim3(32, 8)>>>(Wfc2, w2hi, w2lo, HDIM, HDIM);

    // 1) qkv = x @ Wqkv + bqkv
    gemm_mma_bf16x3<false><<<dim3(3 * HDIM / 128, M / 128), 256, GSMEM>>>(
        xhi, xlo, w1hi, w1lo, bqkv, qkv, M, 3 * HDIM, HDIM);

    // 2) RoPE + head scatter -> bf16 hi/lo (q pre-scaled)
    rope_scatter<<<M, 256>>>(qkv, cosT, sinT, qh, ql, kh, kl, vh, vl);

    // 3) tensor-core causal flash attention -> split Y
    flash_attn_mma<<<dim3(LSEQ / 64, BATCH * NHEADS), 128, ASMEM>>>(
        qh, ql, kh, kl, vh, vl, yhi, ylo);

    // 4) out = silu(y @ Wfc2 + bfc2)
    gemm_mma_bf16x3<true><<<dim3(HDIM / 128, M / 128), 256, GSMEM>>>(
        yhi, ylo, w2hi, w2lo, bfc2, out, M, HDIM, HDIM);
}